// round 4
// baseline (speedup 1.0000x reference)
#include <cuda_runtime.h>
#include <mma.h>
#include <cstdint>
#include <math.h>

using namespace nvcuda;

#define HEADS   8
#define LEVELS  4
#define POINTS  4
#define ED      256
#define HD      32
#define BSZ     2
#define NQ      11253
#define MROWS   (BSZ * NQ)   // 22506
#define MTILES  ((MROWS + 127) / 128)  // 176

// ---------------------------------------------------------------------------
// Scratch (static device arrays; allocation-free per harness rules)
// ---------------------------------------------------------------------------
__device__ float g_v[MROWS * ED];
__device__ float g_off[MROWS * ED];
__device__ float g_attn[MROWS * HEADS * LEVELS * POINTS];
__device__ float g_samp[MROWS * ED];
__device__ float g_wt_val[256 * 256];   // W_val^T  [N=256, K=256]
__device__ float g_wt_off[256 * 256];   // W_off^T
__device__ float g_wt_attn[128 * 256];  // W_attn^T [N=128, K=256]
__device__ float g_wt_out[256 * 256];   // W_out^T

__device__ __forceinline__ float cvt_tf32f(float x) {
    uint32_t r;
    asm("cvt.rna.tf32.f32 %0, %1;" : "=r"(r) : "f"(x));
    return __uint_as_float(r);
}

// ---------------------------------------------------------------------------
// Transpose all 4 weight matrices: Wt[n*256 + k] = W[k*N + n]   (K = 256)
// grid (8, 8, 4), block (32, 8). z=2 (W_attn) has N=128.
// ---------------------------------------------------------------------------
__global__ void transpose4(const float* __restrict__ W0, const float* __restrict__ W1,
                           const float* __restrict__ W2, const float* __restrict__ W3,
                           float* __restrict__ T0, float* __restrict__ T1,
                           float* __restrict__ T2, float* __restrict__ T3)
{
    __shared__ float t[32][33];
    const float* W; float* T; int N;
    switch (blockIdx.z) {
        case 0:  W = W0; T = T0; N = 256; break;
        case 1:  W = W1; T = T1; N = 256; break;
        case 2:  W = W2; T = T2; N = 128; break;
        default: W = W3; T = T3; N = 256; break;
    }
    const int nx = blockIdx.x * 32;
    const int ky = blockIdx.y * 32;
    if (nx >= N) return;
    const int tx = threadIdx.x, ty = threadIdx.y;
    #pragma unroll
    for (int j = 0; j < 32; j += 8)
        t[ty + j][tx] = W[(size_t)(ky + ty + j) * N + nx + tx];
    __syncthreads();
    #pragma unroll
    for (int j = 0; j < 32; j += 8)
        T[(size_t)(nx + ty + j) * 256 + ky + tx] = t[tx][ty + j];
}

// ---------------------------------------------------------------------------
// wmma tf32 GEMM: C[M, NT] = A[M, 256] @ Wt[NT, 256]^T + bias (+ res)
// CTA tile 128x64, BK=32, 256 threads = 8 warps (4m x 2n), warp tile 32x32.
// grid = (NT/64, MTILES). Inputs pre-rounded to tf32 (rna) in smem.
// ---------------------------------------------------------------------------
template<bool RES>
__global__ void __launch_bounds__(256) gemm_wmma(
    const float* __restrict__ A,
    const float* __restrict__ Wt,
    const float* __restrict__ bias,
    const float* __restrict__ res,
    float* __restrict__ C, int M, int NT)
{
    extern __shared__ char smraw[];
    float* sA    = (float*)smraw;            // [128][36]  (18432 B)
    float* sB    = sA + 128 * 36;            // [64][36]   ( 9216 B)
    float* stage = (float*)smraw;            // [128][68]  (34816 B, epilogue alias)

    const int tid  = threadIdx.x;            // 0..255
    const int warp = tid >> 5;
    const int wm   = warp & 3;               // 0..3  (rows wm*32)
    const int wn   = warp >> 2;              // 0..1  (cols wn*32)
    const int m0   = blockIdx.y * 128;
    const int n0   = blockIdx.x * 64;

    wmma::fragment<wmma::accumulator, 16, 16, 8, float> acc[2][2];
    #pragma unroll
    for (int i = 0; i < 2; i++)
        #pragma unroll
        for (int j = 0; j < 2; j++)
            wmma::fill_fragment(acc[i][j], 0.0f);

    for (int kc = 0; kc < 8; kc++) {
        const int k0 = kc * 32;
        // ---- A tile: 128x32 -> tf32(rna) in sA ----
        #pragma unroll
        for (int it = 0; it < 4; it++) {
            const int idx = it * 256 + tid;       // float4 id, 0..1023
            const int row = idx >> 3, c4 = idx & 7;
            float4 v = make_float4(0.f, 0.f, 0.f, 0.f);
            const int m = m0 + row;
            if (m < M)
                v = *(const float4*)(A + (size_t)m * 256 + k0 + c4 * 4);
            float* d = &sA[row * 36 + c4 * 4];
            d[0] = cvt_tf32f(v.x); d[1] = cvt_tf32f(v.y);
            d[2] = cvt_tf32f(v.z); d[3] = cvt_tf32f(v.w);
        }
        // ---- B tile: 64x32 (Wt rows n0..n0+63) -> tf32 in sB ----
        #pragma unroll
        for (int it = 0; it < 2; it++) {
            const int idx = it * 256 + tid;       // 0..511
            const int row = idx >> 3, c4 = idx & 7;
            float4 v = *(const float4*)(Wt + (size_t)(n0 + row) * 256 + k0 + c4 * 4);
            float* d = &sB[row * 36 + c4 * 4];
            d[0] = cvt_tf32f(v.x); d[1] = cvt_tf32f(v.y);
            d[2] = cvt_tf32f(v.z); d[3] = cvt_tf32f(v.w);
        }
        __syncthreads();

        #pragma unroll
        for (int ks = 0; ks < 4; ks++) {
            wmma::fragment<wmma::matrix_a, 16, 16, 8, wmma::precision::tf32,
                           wmma::row_major> af[2];
            wmma::fragment<wmma::matrix_b, 16, 16, 8, wmma::precision::tf32,
                           wmma::col_major> bf[2];
            #pragma unroll
            for (int i = 0; i < 2; i++)
                wmma::load_matrix_sync(af[i], &sA[(wm * 32 + i * 16) * 36 + ks * 8], 36);
            #pragma unroll
            for (int j = 0; j < 2; j++)
                wmma::load_matrix_sync(bf[j], &sB[(wn * 32 + j * 16) * 36 + ks * 8], 36);
            #pragma unroll
            for (int i = 0; i < 2; i++)
                #pragma unroll
                for (int j = 0; j < 2; j++)
                    wmma::mma_sync(acc[i][j], af[i], bf[j], acc[i][j]);
        }
        __syncthreads();
    }

    // ---- epilogue: accumulators -> smem stage -> coalesced gmem ----
    #pragma unroll
    for (int i = 0; i < 2; i++)
        #pragma unroll
        for (int j = 0; j < 2; j++)
            wmma::store_matrix_sync(
                &stage[(wm * 32 + i * 16) * 68 + wn * 32 + j * 16],
                acc[i][j], 68, wmma::mem_row_major);
    __syncthreads();

    #pragma unroll
    for (int it = 0; it < 8; it++) {
        const int idx = it * 256 + tid;           // float4 id, 0..2047
        const int row = idx >> 4, c4 = idx & 15;
        const int m = m0 + row;
        if (m < M) {
            float4 v = *(float4*)(&stage[row * 68 + c4 * 4]);
            const int n = n0 + c4 * 4;
            const float4 bb = *(const float4*)(bias + n);
            v.x += bb.x; v.y += bb.y; v.z += bb.z; v.w += bb.w;
            if (RES) {
                const float4 rr = *(const float4*)(res + (size_t)m * NT + n);
                v.x += rr.x; v.y += rr.y; v.z += rr.z; v.w += rr.w;
            }
            *(float4*)(C + (size_t)m * NT + n) = v;
        }
    }
}

// ---------------------------------------------------------------------------
// MSDA sampling (unchanged): one block per (b,q); one warp per head.
// ---------------------------------------------------------------------------
__global__ void msda_sample(const float* __restrict__ v,
                            const float* __restrict__ off,
                            const float* __restrict__ attn,
                            const float* __restrict__ refp,
                            float* __restrict__ samp)
{
    __shared__ int4   sIdx[HEADS][16];
    __shared__ float4 sW[HEADS][16];

    const int row  = blockIdx.x;           // b*NQ + q
    const int b    = row / NQ;
    const int h    = threadIdx.x >> 5;     // warp = head
    const int lane = threadIdx.x & 31;

    float logit = -1e30f;
    if (lane < 16) logit = attn[(size_t)row * (HEADS * 16) + h * 16 + lane];
    float mx = logit;
    #pragma unroll
    for (int o = 8; o >= 1; o >>= 1)
        mx = fmaxf(mx, __shfl_xor_sync(0xffffffffu, mx, o, 16));
    float e = (lane < 16) ? __expf(logit - mx) : 0.f;
    float s = e;
    #pragma unroll
    for (int o = 8; o >= 1; o >>= 1)
        s += __shfl_xor_sync(0xffffffffu, s, o, 16);

    if (lane < 16) {
        const float w = e / s;
        const int   j = lane;
        const int   l = j >> 2;

        const int HW[4]  = {92, 46, 23, 12};
        const int LST[4] = {0, 8464, 10580, 11109};
        const int   Ww = HW[l], Hh = HW[l], st = LST[l];
        const float fW = (float)Ww, fH = (float)Hh;

        const float2 rp = *reinterpret_cast<const float2*>(
            refp + (size_t)row * (LEVELS * 2) + 2 * l);
        const float2 of = *reinterpret_cast<const float2*>(
            off + (size_t)row * ED + h * 32 + 2 * j);

        const float x = (rp.x + of.x / fW) * fW - 0.5f;
        const float y = (rp.y + of.y / fH) * fH - 0.5f;

        const float x0f = floorf(x), y0f = floorf(y);
        const int   x0 = (int)x0f,   y0 = (int)y0f;
        const float wx1 = x - x0f,   wy1 = y - y0f;
        const float wx0 = 1.f - wx1, wy0 = 1.f - wy1;

        const bool xi0 = (x0 >= 0) && (x0 < Ww);
        const bool xi1 = (x0 + 1 >= 0) && (x0 + 1 < Ww);
        const bool yi0 = (y0 >= 0) && (y0 < Hh);
        const bool yi1 = (y0 + 1 >= 0) && (y0 + 1 < Hh);

        const int xc0 = min(max(x0, 0), Ww - 1);
        const int xc1 = min(max(x0 + 1, 0), Ww - 1);
        const int yc0 = min(max(y0, 0), Hh - 1);
        const int yc1 = min(max(y0 + 1, 0), Hh - 1);

        const int base = (b * NQ + st) * ED + h * 32;
        const int r0   = yc0 * Ww * ED;
        const int r1   = yc1 * Ww * ED;

        int4 idx;
        idx.x = base + r0 + xc0 * ED;
        idx.y = base + r0 + xc1 * ED;
        idx.z = base + r1 + xc0 * ED;
        idx.w = base + r1 + xc1 * ED;

        float4 cw;
        cw.x = (xi0 && yi0) ? w * wx0 * wy0 : 0.f;
        cw.y = (xi1 && yi0) ? w * wx1 * wy0 : 0.f;
        cw.z = (xi0 && yi1) ? w * wx0 * wy1 : 0.f;
        cw.w = (xi1 && yi1) ? w * wx1 * wy1 : 0.f;

        sIdx[h][j] = idx;
        sW[h][j]   = cw;
    }
    __syncwarp();

    float acc = 0.f;
    #pragma unroll
    for (int j = 0; j < 16; j++) {
        const int4   id = sIdx[h][j];
        const float4 w  = sW[h][j];
        acc += w.x * __ldg(v + id.x + lane);
        acc += w.y * __ldg(v + id.y + lane);
        acc += w.z * __ldg(v + id.z + lane);
        acc += w.w * __ldg(v + id.w + lane);
    }

    samp[(size_t)row * ED + h * 32 + lane] = acc;
}

// ---------------------------------------------------------------------------
// Launch
// ---------------------------------------------------------------------------
extern "C" void kernel_launch(void* const* d_in, const int* in_sizes, int n_in,
                              void* d_out, int out_size)
{
    const float* query  = (const float*)d_in[0];
    const float* value  = (const float*)d_in[1];
    const float* refpts = (const float*)d_in[2];
    // d_in[3] = spatial_shapes (int32) — compile-time constants here
    const float* W_val  = (const float*)d_in[4];
    const float* b_val  = (const float*)d_in[5];
    const float* W_off  = (const float*)d_in[6];
    const float* b_off  = (const float*)d_in[7];
    const float* W_attn = (const float*)d_in[8];
    const float* b_attn = (const float*)d_in[9];
    const float* W_out  = (const float*)d_in[10];
    const float* b_out  = (const float*)d_in[11];
    float* out = (float*)d_out;

    float *pv, *poff, *pattn, *psamp;
    float *twv, *two, *twa, *twu;
    cudaGetSymbolAddress((void**)&pv,    g_v);
    cudaGetSymbolAddress((void**)&poff,  g_off);
    cudaGetSymbolAddress((void**)&pattn, g_attn);
    cudaGetSymbolAddress((void**)&psamp, g_samp);
    cudaGetSymbolAddress((void**)&twv,   g_wt_val);
    cudaGetSymbolAddress((void**)&two,   g_wt_off);
    cudaGetSymbolAddress((void**)&twa,   g_wt_attn);
    cudaGetSymbolAddress((void**)&twu,   g_wt_out);

    const int SMEM = 128 * 68 * 4;  // 34816 B (epilogue stage is the max user)

    // 1) transpose weights
    transpose4<<<dim3(8, 8, 4), dim3(32, 8)>>>(W_val, W_off, W_attn, W_out,
                                               twv, two, twa, twu);

    // 2) projections (wmma tf32)
    gemm_wmma<false><<<dim3(4, MTILES), 256, SMEM>>>(value, twv, b_val,  nullptr, pv,    MROWS, 256);
    gemm_wmma<false><<<dim3(4, MTILES), 256, SMEM>>>(query, two, b_off,  nullptr, poff,  MROWS, 256);
    gemm_wmma<false><<<dim3(2, MTILES), 256, SMEM>>>(query, twa, b_attn, nullptr, pattn, MROWS, 128);

    // 3) sampling
    msda_sample<<<MROWS, HEADS * 32>>>(pv, poff, pattn, refpts, psamp);

    // 4) output projection + residual
    gemm_wmma<true><<<dim3(4, MTILES), 256, SMEM>>>(psamp, twu, b_out, query, out, MROWS, 256);
}

// round 5
// speedup vs baseline: 1.4764x; 1.4764x over previous
#include <cuda_runtime.h>
#include <mma.h>
#include <cstdint>
#include <math.h>

using namespace nvcuda;

#define HEADS   8
#define LEVELS  4
#define POINTS  4
#define ED      256
#define HD      32
#define BSZ     2
#define NQ      11253
#define MROWS   (BSZ * NQ)   // 22506
#define MTILES  ((MROWS + 127) / 128)  // 176

// ---------------------------------------------------------------------------
// Scratch (static device arrays; allocation-free per harness rules)
// ---------------------------------------------------------------------------
__device__ float g_v[MROWS * ED];       // value-proj output (fp32)
__device__ float g_off[MROWS * ED];     // offset-proj output (fp32)
__device__ float g_attn[MROWS * 128];   // attn logits (fp32)
__device__ float g_samp[MROWS * ED];    // sampler output (tf32-rounded)
__device__ float g_qr[MROWS * ED];      // query  rounded to tf32
__device__ float g_vr[MROWS * ED];      // value  rounded to tf32
__device__ float g_wt_val[256 * 256];   // W_val^T  [N,K] tf32-rounded
__device__ float g_wt_off[256 * 256];
__device__ float g_wt_attn[128 * 256];
__device__ float g_wt_out[256 * 256];

__device__ __forceinline__ float cvt_tf32f(float x) {
    uint32_t r;
    asm("cvt.rna.tf32.f32 %0, %1;" : "=r"(r) : "f"(x));
    return __uint_as_float(r);
}

__device__ __forceinline__ uint32_t smem_u32(const void* p) {
    uint32_t a;
    asm("{ .reg .u64 t; cvta.to.shared.u64 t, %1; cvt.u32.u64 %0, t; }"
        : "=r"(a) : "l"(p));
    return a;
}

__device__ __forceinline__ void cp_async16(uint32_t dst, const void* src) {
    asm volatile("cp.async.cg.shared.global [%0], [%1], 16;"
                 :: "r"(dst), "l"(src) : "memory");
}
#define CP_COMMIT() asm volatile("cp.async.commit_group;" ::: "memory")
#define CP_WAIT(N)  asm volatile("cp.async.wait_group %0;" :: "n"(N) : "memory")

// ---------------------------------------------------------------------------
// Pre-round fp32 -> tf32(rna) elementwise (float4 grid-stride)
// ---------------------------------------------------------------------------
__global__ void round_tf32(const float* __restrict__ in, float* __restrict__ out,
                           int n4)
{
    for (int i = blockIdx.x * blockDim.x + threadIdx.x; i < n4;
         i += gridDim.x * blockDim.x) {
        float4 v = *(const float4*)(in + (size_t)i * 4);
        v.x = cvt_tf32f(v.x); v.y = cvt_tf32f(v.y);
        v.z = cvt_tf32f(v.z); v.w = cvt_tf32f(v.w);
        *(float4*)(out + (size_t)i * 4) = v;
    }
}

// ---------------------------------------------------------------------------
// Transpose + round weights: Wt[n*256 + k] = tf32(W[k*N + n])
// ---------------------------------------------------------------------------
__global__ void transpose4(const float* __restrict__ W0, const float* __restrict__ W1,
                           const float* __restrict__ W2, const float* __restrict__ W3,
                           float* __restrict__ T0, float* __restrict__ T1,
                           float* __restrict__ T2, float* __restrict__ T3)
{
    __shared__ float t[32][33];
    const float* W; float* T; int N;
    switch (blockIdx.z) {
        case 0:  W = W0; T = T0; N = 256; break;
        case 1:  W = W1; T = T1; N = 256; break;
        case 2:  W = W2; T = T2; N = 128; break;
        default: W = W3; T = T3; N = 256; break;
    }
    const int nx = blockIdx.x * 32;
    const int ky = blockIdx.y * 32;
    if (nx >= N) return;
    const int tx = threadIdx.x, ty = threadIdx.y;
    #pragma unroll
    for (int j = 0; j < 32; j += 8)
        t[ty + j][tx] = cvt_tf32f(W[(size_t)(ky + ty + j) * N + nx + tx]);
    __syncthreads();
    #pragma unroll
    for (int j = 0; j < 32; j += 8)
        T[(size_t)(nx + ty + j) * 256 + ky + tx] = t[tx][ty + j];
}

// ---------------------------------------------------------------------------
// wmma tf32 GEMM (2-stage cp.async pipeline):
//   C[M, NT] = A[M,256] @ Wt[NT,256]^T + bias (+ res)
// Inputs A, Wt are pre-rounded to tf32. CTA tile 128x128, BK=32, 256 thr
// (8 warps, 4m x 2n, warp tile 32x64). grid = (NT/128, MTILES).
// smem: 2 stages x (A 128x36 + B 128x36) fp32 = 73728 B; epilogue aliases it.
// ---------------------------------------------------------------------------
template<bool RES>
__global__ void __launch_bounds__(256, 1) gemm_wmma(
    const float* __restrict__ A,
    const float* __restrict__ Wt,
    const float* __restrict__ bias,
    const float* __restrict__ res,
    float* __restrict__ C, int M, int NT)
{
    extern __shared__ float sm[];
    const int STAGE = 128 * 36 * 2;          // floats per stage (A + B)

    const int tid  = threadIdx.x;
    const int warp = tid >> 5;
    const int wm   = warp & 3;               // 0..3 -> rows wm*32
    const int wn   = warp >> 2;              // 0..1 -> cols wn*64
    const int m0   = blockIdx.y * 128;
    const int n0   = blockIdx.x * 128;
    const uint32_t smb = smem_u32(sm);

    // per-thread chunk coords (16B chunks): 1024 per matrix, 4 per thread
    const int lrow = tid >> 1;               // reused pattern: idx=i*256+tid
    (void)lrow;

    wmma::fragment<wmma::accumulator, 16, 16, 8, float> acc[2][4];
    #pragma unroll
    for (int i = 0; i < 2; i++)
        #pragma unroll
        for (int j = 0; j < 4; j++)
            wmma::fill_fragment(acc[i][j], 0.0f);

    auto load_stage = [&](int kc, int s) {
        const int k0 = kc * 32;
        const uint32_t sbase = smb + (uint32_t)(s * STAGE) * 4u;
        #pragma unroll
        for (int i = 0; i < 4; i++) {
            const int idx = i * 256 + tid;    // 0..1023
            const int r = idx >> 3, c = idx & 7;
            const int m = min(m0 + r, M - 1); // clamp; bad rows never stored
            cp_async16(sbase + (uint32_t)(r * 36 + c * 4) * 4u,
                       A + (size_t)m * 256 + k0 + c * 4);
        }
        #pragma unroll
        for (int i = 0; i < 4; i++) {
            const int idx = i * 256 + tid;
            const int r = idx >> 3, c = idx & 7;
            cp_async16(sbase + (uint32_t)(128 * 36 + r * 36 + c * 4) * 4u,
                       Wt + (size_t)(n0 + r) * 256 + k0 + c * 4);
        }
        CP_COMMIT();
    };

    load_stage(0, 0);

    for (int kc = 0; kc < 8; kc++) {
        const int s = kc & 1;
        if (kc < 7) {
            load_stage(kc + 1, s ^ 1);
            CP_WAIT(1);
        } else {
            CP_WAIT(0);
        }
        __syncthreads();

        const float* sA = sm + s * STAGE;
        const float* sB = sA + 128 * 36;

        #pragma unroll
        for (int ks = 0; ks < 4; ks++) {
            wmma::fragment<wmma::matrix_a, 16, 16, 8, wmma::precision::tf32,
                           wmma::row_major> af[2];
            wmma::fragment<wmma::matrix_b, 16, 16, 8, wmma::precision::tf32,
                           wmma::col_major> bf[4];
            #pragma unroll
            for (int i = 0; i < 2; i++)
                wmma::load_matrix_sync(af[i], &sA[(wm * 32 + i * 16) * 36 + ks * 8], 36);
            #pragma unroll
            for (int j = 0; j < 4; j++)
                wmma::load_matrix_sync(bf[j], &sB[(wn * 64 + j * 16) * 36 + ks * 8], 36);
            #pragma unroll
            for (int i = 0; i < 2; i++)
                #pragma unroll
                for (int j = 0; j < 4; j++)
                    wmma::mma_sync(acc[i][j], af[i], bf[j], acc[i][j]);
        }
        __syncthreads();
    }

    // ---- epilogue: accumulators -> smem stage (stride 132) -> gmem ----
    float* stage = sm;                        // alias, 128*132 = 67584 B
    #pragma unroll
    for (int i = 0; i < 2; i++)
        #pragma unroll
        for (int j = 0; j < 4; j++)
            wmma::store_matrix_sync(
                &stage[(wm * 32 + i * 16) * 132 + wn * 64 + j * 16],
                acc[i][j], 132, wmma::mem_row_major);
    __syncthreads();

    #pragma unroll
    for (int it = 0; it < 16; it++) {
        const int idx = it * 256 + tid;       // float4 id, 0..4095
        const int row = idx >> 5, c4 = idx & 31;
        const int m = m0 + row;
        if (m < M) {
            float4 v = *(float4*)(&stage[row * 132 + c4 * 4]);
            const int n = n0 + c4 * 4;
            const float4 bb = *(const float4*)(bias + n);
            v.x += bb.x; v.y += bb.y; v.z += bb.z; v.w += bb.w;
            if (RES) {
                const float4 rr = *(const float4*)(res + (size_t)m * NT + n);
                v.x += rr.x; v.y += rr.y; v.z += rr.z; v.w += rr.w;
            }
            *(float4*)(C + (size_t)m * NT + n) = v;
        }
    }
}

// ---------------------------------------------------------------------------
// MSDA sampling v3: paired-lane float2 gathers.
// One block per (b,q); one warp per head. Lane halves (p=0/1) fetch
// corner pairs {0,2} / {1,3}; each lane covers 2 head-dims via LDG.64.
// Combine halves with one shfl_xor(16). Output pre-rounded to tf32.
// ---------------------------------------------------------------------------
__global__ void msda_sample(const float* __restrict__ v,
                            const float* __restrict__ off,
                            const float* __restrict__ attn,
                            const float* __restrict__ refp,
                            float* __restrict__ samp)
{
    __shared__ int2   sOff[HEADS][16][2];
    __shared__ float2 sWp[HEADS][16][2];

    const int row  = blockIdx.x;           // b*NQ + q
    const int b    = row / NQ;
    const int h    = threadIdx.x >> 5;     // warp = head
    const int lane = threadIdx.x & 31;

    // ---- softmax over 16 logits (lanes 0..15) ----
    float logit = -1e30f;
    if (lane < 16) logit = attn[(size_t)row * (HEADS * 16) + h * 16 + lane];
    float mx = logit;
    #pragma unroll
    for (int o = 8; o >= 1; o >>= 1)
        mx = fmaxf(mx, __shfl_xor_sync(0xffffffffu, mx, o, 16));
    float e = (lane < 16) ? __expf(logit - mx) : 0.f;
    float s = e;
    #pragma unroll
    for (int o = 8; o >= 1; o >>= 1)
        s += __shfl_xor_sync(0xffffffffu, s, o, 16);

    if (lane < 16) {
        const float w = e / s;
        const int   j = lane;
        const int   l = j >> 2;

        const int HW[4]  = {92, 46, 23, 12};
        const int LST[4] = {0, 8464, 10580, 11109};
        const int   Ww = HW[l], Hh = HW[l], st = LST[l];
        const float fW = (float)Ww, fH = (float)Hh;

        const float2 rp = *reinterpret_cast<const float2*>(
            refp + (size_t)row * (LEVELS * 2) + 2 * l);
        const float2 of = *reinterpret_cast<const float2*>(
            off + (size_t)row * ED + h * 32 + 2 * j);

        const float x = (rp.x + of.x / fW) * fW - 0.5f;
        const float y = (rp.y + of.y / fH) * fH - 0.5f;

        const float x0f = floorf(x), y0f = floorf(y);
        const int   x0 = (int)x0f,   y0 = (int)y0f;
        const float wx1 = x - x0f,   wy1 = y - y0f;
        const float wx0 = 1.f - wx1, wy0 = 1.f - wy1;

        const bool xi0 = (x0 >= 0) && (x0 < Ww);
        const bool xi1 = (x0 + 1 >= 0) && (x0 + 1 < Ww);
        const bool yi0 = (y0 >= 0) && (y0 < Hh);
        const bool yi1 = (y0 + 1 >= 0) && (y0 + 1 < Hh);

        const int xc0 = min(max(x0, 0), Ww - 1);
        const int xc1 = min(max(x0 + 1, 0), Ww - 1);
        const int yc0 = min(max(y0, 0), Hh - 1);
        const int yc1 = min(max(y0 + 1, 0), Hh - 1);

        const int base = (b * NQ + st) * ED + h * 32;
        const int r0   = yc0 * Ww * ED;
        const int r1   = yc1 * Ww * ED;

        const int i00 = base + r0 + xc0 * ED;   // corner (x0,y0)
        const int i01 = base + r0 + xc1 * ED;   // corner (x1,y0)
        const int i10 = base + r1 + xc0 * ED;   // corner (x0,y1)
        const int i11 = base + r1 + xc1 * ED;   // corner (x1,y1)

        const float w00 = (xi0 && yi0) ? w * wx0 * wy0 : 0.f;
        const float w01 = (xi1 && yi0) ? w * wx1 * wy0 : 0.f;
        const float w10 = (xi0 && yi1) ? w * wx0 * wy1 : 0.f;
        const float w11 = (xi1 && yi1) ? w * wx1 * wy1 : 0.f;

        sOff[h][j][0] = make_int2(i00, i10);    // half p=0: corners 00, 10
        sOff[h][j][1] = make_int2(i01, i11);    // half p=1: corners 01, 11
        sWp[h][j][0]  = make_float2(w00, w10);
        sWp[h][j][1]  = make_float2(w01, w11);
    }
    __syncwarp();

    const int p    = lane >> 4;
    const int sub2 = (lane & 15) * 2;
    const float* vb = v + sub2;

    float ax = 0.f, ay = 0.f;
    #pragma unroll
    for (int j = 0; j < 16; j++) {
        const int2   o  = sOff[h][j][p];
        const float2 ww = sWp[h][j][p];
        const float2 v0 = *(const float2*)(vb + o.x);
        const float2 v1 = *(const float2*)(vb + o.y);
        ax += ww.x * v0.x + ww.y * v1.x;
        ay += ww.x * v0.y + ww.y * v1.y;
    }
    ax += __shfl_xor_sync(0xffffffffu, ax, 16);
    ay += __shfl_xor_sync(0xffffffffu, ay, 16);

    if (lane < 16) {
        float2 o;
        o.x = cvt_tf32f(ax);                 // pre-round for out-proj GEMM
        o.y = cvt_tf32f(ay);
        *(float2*)(samp + (size_t)row * ED + h * 32 + sub2) = o;
    }
}

// ---------------------------------------------------------------------------
// Launch
// ---------------------------------------------------------------------------
extern "C" void kernel_launch(void* const* d_in, const int* in_sizes, int n_in,
                              void* d_out, int out_size)
{
    const float* query  = (const float*)d_in[0];
    const float* value  = (const float*)d_in[1];
    const float* refpts = (const float*)d_in[2];
    // d_in[3] = spatial_shapes (int32) — compile-time constants here
    const float* W_val  = (const float*)d_in[4];
    const float* b_val  = (const float*)d_in[5];
    const float* W_off  = (const float*)d_in[6];
    const float* b_off  = (const float*)d_in[7];
    const float* W_attn = (const float*)d_in[8];
    const float* b_attn = (const float*)d_in[9];
    const float* W_out  = (const float*)d_in[10];
    const float* b_out  = (const float*)d_in[11];
    float* out = (float*)d_out;

    float *pv, *poff, *pattn, *psamp, *pqr, *pvr;
    float *twv, *two, *twa, *twu;
    cudaGetSymbolAddress((void**)&pv,    g_v);
    cudaGetSymbolAddress((void**)&poff,  g_off);
    cudaGetSymbolAddress((void**)&pattn, g_attn);
    cudaGetSymbolAddress((void**)&psamp, g_samp);
    cudaGetSymbolAddress((void**)&pqr,   g_qr);
    cudaGetSymbolAddress((void**)&pvr,   g_vr);
    cudaGetSymbolAddress((void**)&twv,   g_wt_val);
    cudaGetSymbolAddress((void**)&two,   g_wt_off);
    cudaGetSymbolAddress((void**)&twa,   g_wt_attn);
    cudaGetSymbolAddress((void**)&twu,   g_wt_out);

    const int SMEM = 2 * 128 * 36 * 2 * 4;   // 73728 B
    cudaFuncSetAttribute(gemm_wmma<false>,
                         cudaFuncAttributeMaxDynamicSharedMemorySize, SMEM);
    cudaFuncSetAttribute(gemm_wmma<true>,
                         cudaFuncAttributeMaxDynamicSharedMemorySize, SMEM);

    // 1) prep: round inputs to tf32; transpose+round weights
    const int N4 = MROWS * ED / 4;           // 1,440,384 float4s
    round_tf32<<<1184, 256>>>(query, pqr, N4);
    round_tf32<<<1184, 256>>>(value, pvr, N4);
    transpose4<<<dim3(8, 8, 4), dim3(32, 8)>>>(W_val, W_off, W_attn, W_out,
                                               twv, two, twa, twu);

    // 2) projections (wmma tf32, pipelined)
    gemm_wmma<false><<<dim3(2, MTILES), 256, SMEM>>>(pvr, twv, b_val,  nullptr, pv,    MROWS, 256);
    gemm_wmma<false><<<dim3(2, MTILES), 256, SMEM>>>(pqr, two, b_off,  nullptr, poff,  MROWS, 256);
    gemm_wmma<false><<<dim3(1, MTILES), 256, SMEM>>>(pqr, twa, b_attn, nullptr, pattn, MROWS, 128);

    // 3) sampling
    msda_sample<<<MROWS, HEADS * 32>>>(pv, poff, pattn, refpts, psamp);

    // 4) output projection + residual (residual = original fp32 query)
    gemm_wmma<true><<<dim3(2, MTILES), 256, SMEM>>>(psamp, twu, b_out, query, out, MROWS, 256);
}

// round 6
// speedup vs baseline: 1.7559x; 1.1893x over previous
#include <cuda_runtime.h>
#include <mma.h>
#include <cstdint>
#include <math.h>

using namespace nvcuda;

#define HEADS   8
#define LEVELS  4
#define POINTS  4
#define ED      256
#define HD      32
#define BSZ     2
#define NQ      11253
#define MROWS   (BSZ * NQ)   // 22506
#define MTILES  ((MROWS + 127) / 128)  // 176

// ---------------------------------------------------------------------------
// Scratch (static device arrays; allocation-free per harness rules)
// ---------------------------------------------------------------------------
__device__ float g_v[MROWS * ED];       // value-proj output (fp32)
__device__ float g_off[MROWS * ED];     // offset-proj output (fp32)
__device__ float g_attn[MROWS * 128];   // attn logits (fp32)
__device__ float g_samp[MROWS * ED];    // sampler output (tf32-rounded)
__device__ float g_qr[MROWS * ED];      // query rounded to tf32
__device__ float g_vr[MROWS * ED];      // value rounded to tf32
__device__ float g_wt_val[256 * 256];   // W_val^T  [N,K] tf32-rounded
__device__ float g_wt_off[256 * 256];
__device__ float g_wt_attn[128 * 256];
__device__ float g_wt_out[256 * 256];

__device__ __forceinline__ float cvt_tf32f(float x) {
    uint32_t r;
    asm("cvt.rna.tf32.f32 %0, %1;" : "=r"(r) : "f"(x));
    return __uint_as_float(r);
}

__device__ __forceinline__ uint32_t smem_u32(const void* p) {
    uint32_t a;
    asm("{ .reg .u64 t; cvta.to.shared.u64 t, %1; cvt.u32.u64 %0, t; }"
        : "=r"(a) : "l"(p));
    return a;
}

__device__ __forceinline__ void cp_async16(uint32_t dst, const void* src) {
    asm volatile("cp.async.cg.shared.global [%0], [%1], 16;"
                 :: "r"(dst), "l"(src) : "memory");
}
#define CP_COMMIT() asm volatile("cp.async.commit_group;" ::: "memory")
#define CP_WAIT(N)  asm volatile("cp.async.wait_group %0;" :: "n"(N) : "memory")

// ---------------------------------------------------------------------------
// Pre-round fp32 -> tf32(rna), two tensors in one launch
// ---------------------------------------------------------------------------
__global__ void round2_tf32(const float* __restrict__ in0, float* __restrict__ out0,
                            const float* __restrict__ in1, float* __restrict__ out1,
                            int n4)
{
    for (int i = blockIdx.x * blockDim.x + threadIdx.x; i < 2 * n4;
         i += gridDim.x * blockDim.x) {
        const float* in  = (i < n4) ? in0  : in1;
        float*       out = (i < n4) ? out0 : out1;
        const int    k   = (i < n4) ? i : (i - n4);
        float4 v = *(const float4*)(in + (size_t)k * 4);
        v.x = cvt_tf32f(v.x); v.y = cvt_tf32f(v.y);
        v.z = cvt_tf32f(v.z); v.w = cvt_tf32f(v.w);
        *(float4*)(out + (size_t)k * 4) = v;
    }
}

// ---------------------------------------------------------------------------
// Transpose + round weights: Wt[n*256 + k] = tf32(W[k*N + n])
// ---------------------------------------------------------------------------
__global__ void transpose4(const float* __restrict__ W0, const float* __restrict__ W1,
                           const float* __restrict__ W2, const float* __restrict__ W3,
                           float* __restrict__ T0, float* __restrict__ T1,
                           float* __restrict__ T2, float* __restrict__ T3)
{
    __shared__ float t[32][33];
    const float* W; float* T; int N;
    switch (blockIdx.z) {
        case 0:  W = W0; T = T0; N = 256; break;
        case 1:  W = W1; T = T1; N = 256; break;
        case 2:  W = W2; T = T2; N = 128; break;
        default: W = W3; T = T3; N = 256; break;
    }
    const int nx = blockIdx.x * 32;
    const int ky = blockIdx.y * 32;
    if (nx >= N) return;
    const int tx = threadIdx.x, ty = threadIdx.y;
    #pragma unroll
    for (int j = 0; j < 32; j += 8)
        t[ty + j][tx] = cvt_tf32f(W[(size_t)(ky + ty + j) * N + nx + tx]);
    __syncthreads();
    #pragma unroll
    for (int j = 0; j < 32; j += 8)
        T[(size_t)(nx + ty + j) * 256 + ky + tx] = t[tx][ty + j];
}

// ---------------------------------------------------------------------------
// Core wmma tf32 GEMM tile: CTA 128(M) x 64(N), BK=32, 256 thr,
// 8 warps (4m x 2n), warp tile 32x32. 2-stage cp.async pipeline.
// smem: 2 x (128x36 + 64x36) floats = 55296 B. Epilogue aliases stage 0.
// ---------------------------------------------------------------------------
template<bool RES>
__device__ __forceinline__ void gemm_tile(
    float* sm, const float* __restrict__ A, const float* __restrict__ Wt,
    const float* __restrict__ bias, const float* __restrict__ res,
    float* __restrict__ C, int M, int NT, int m0, int n0)
{
    const int STAGE_A = 128 * 36;
    const int STAGE_B = 64 * 36;
    const int STAGE   = STAGE_A + STAGE_B;   // 6912 floats

    const int tid  = threadIdx.x;
    const int warp = tid >> 5;
    const int wm   = warp & 3;               // rows wm*32
    const int wn   = warp >> 2;              // cols wn*32
    const uint32_t smb = smem_u32(sm);

    wmma::fragment<wmma::accumulator, 16, 16, 8, float> acc[2][2];
    #pragma unroll
    for (int i = 0; i < 2; i++)
        #pragma unroll
        for (int j = 0; j < 2; j++)
            wmma::fill_fragment(acc[i][j], 0.0f);

    auto load_stage = [&](int kc, int s) {
        const int k0 = kc * 32;
        const uint32_t sbase = smb + (uint32_t)(s * STAGE) * 4u;
        #pragma unroll
        for (int i = 0; i < 4; i++) {
            const int idx = i * 256 + tid;    // 0..1023
            const int r = idx >> 3, c = idx & 7;
            const int m = min(m0 + r, M - 1);
            cp_async16(sbase + (uint32_t)(r * 36 + c * 4) * 4u,
                       A + (size_t)m * 256 + k0 + c * 4);
        }
        #pragma unroll
        for (int i = 0; i < 2; i++) {
            const int idx = i * 256 + tid;    // 0..511
            const int r = idx >> 3, c = idx & 7;
            cp_async16(sbase + (uint32_t)(STAGE_A + r * 36 + c * 4) * 4u,
                       Wt + (size_t)(n0 + r) * 256 + k0 + c * 4);
        }
        CP_COMMIT();
    };

    load_stage(0, 0);

    for (int kc = 0; kc < 8; kc++) {
        const int s = kc & 1;
        if (kc < 7) {
            load_stage(kc + 1, s ^ 1);
            CP_WAIT(1);
        } else {
            CP_WAIT(0);
        }
        __syncthreads();

        const float* sA = sm + s * STAGE;
        const float* sB = sA + STAGE_A;

        #pragma unroll
        for (int ks = 0; ks < 4; ks++) {
            wmma::fragment<wmma::matrix_a, 16, 16, 8, wmma::precision::tf32,
                           wmma::row_major> af[2];
            wmma::fragment<wmma::matrix_b, 16, 16, 8, wmma::precision::tf32,
                           wmma::col_major> bf[2];
            #pragma unroll
            for (int i = 0; i < 2; i++)
                wmma::load_matrix_sync(af[i], &sA[(wm * 32 + i * 16) * 36 + ks * 8], 36);
            #pragma unroll
            for (int j = 0; j < 2; j++)
                wmma::load_matrix_sync(bf[j], &sB[(wn * 32 + j * 16) * 36 + ks * 8], 36);
            #pragma unroll
            for (int i = 0; i < 2; i++)
                #pragma unroll
                for (int j = 0; j < 2; j++)
                    wmma::mma_sync(acc[i][j], af[i], bf[j], acc[i][j]);
        }
        __syncthreads();
    }

    // ---- epilogue: accumulators -> smem (stride 68) -> gmem ----
    float* stage = sm;                        // 128*68 = 8704 floats, fits
    #pragma unroll
    for (int i = 0; i < 2; i++)
        #pragma unroll
        for (int j = 0; j < 2; j++)
            wmma::store_matrix_sync(
                &stage[(wm * 32 + i * 16) * 68 + wn * 32 + j * 16],
                acc[i][j], 68, wmma::mem_row_major);
    __syncthreads();

    #pragma unroll
    for (int it = 0; it < 8; it++) {
        const int idx = it * 256 + tid;       // float4 id, 0..2047
        const int row = idx >> 4, c4 = idx & 15;
        const int m = m0 + row;
        if (m < M) {
            float4 v = *(float4*)(&stage[row * 68 + c4 * 4]);
            const int n = n0 + c4 * 4;
            const float4 bb = *(const float4*)(bias + n);
            v.x += bb.x; v.y += bb.y; v.z += bb.z; v.w += bb.w;
            if (RES) {
                const float4 rr = *(const float4*)(res + (size_t)m * NT + n);
                v.x += rr.x; v.y += rr.y; v.z += rr.z; v.w += rr.w;
            }
            *(float4*)(C + (size_t)m * NT + n) = v;
        }
    }
}

// ---------------------------------------------------------------------------
// Fused projections: one launch covers value/offset/attn GEMMs.
// grid.x in [0,10): t<4 -> value-proj col-tile t; t<8 -> off-proj (t-4);
// else attn-proj (t-8). grid.y = M tile.
// ---------------------------------------------------------------------------
__global__ void __launch_bounds__(256, 2) gemm_proj_fused(
    const float* __restrict__ Aq,  const float* __restrict__ Av,
    const float* __restrict__ Wv,  const float* __restrict__ bv,  float* __restrict__ Cv,
    const float* __restrict__ Wo,  const float* __restrict__ bo,  float* __restrict__ Co,
    const float* __restrict__ Wa,  const float* __restrict__ ba,  float* __restrict__ Ca,
    int M)
{
    extern __shared__ float sm[];
    const int t  = blockIdx.x;
    const int m0 = blockIdx.y * 128;

    const float *A, *Wt, *bias; float* C; int NT, n0;
    if (t < 4)      { A = Av; Wt = Wv; bias = bv; C = Cv; NT = 256; n0 = t * 64; }
    else if (t < 8) { A = Aq; Wt = Wo; bias = bo; C = Co; NT = 256; n0 = (t - 4) * 64; }
    else            { A = Aq; Wt = Wa; bias = ba; C = Ca; NT = 128; n0 = (t - 8) * 64; }

    gemm_tile<false>(sm, A, Wt, bias, nullptr, C, M, NT, m0, n0);
}

// ---------------------------------------------------------------------------
// Output projection (+ residual): grid (4, MTILES)
// ---------------------------------------------------------------------------
__global__ void __launch_bounds__(256, 2) gemm_out(
    const float* __restrict__ A, const float* __restrict__ Wt,
    const float* __restrict__ bias, const float* __restrict__ res,
    float* __restrict__ C, int M)
{
    extern __shared__ float sm[];
    gemm_tile<true>(sm, A, Wt, bias, res, C, M, 256,
                    blockIdx.y * 128, blockIdx.x * 64);
}

// ---------------------------------------------------------------------------
// MSDA sampling (paired-lane float2, unchanged from R5)
// ---------------------------------------------------------------------------
__global__ void msda_sample(const float* __restrict__ v,
                            const float* __restrict__ off,
                            const float* __restrict__ attn,
                            const float* __restrict__ refp,
                            float* __restrict__ samp)
{
    __shared__ int2   sOff[HEADS][16][2];
    __shared__ float2 sWp[HEADS][16][2];

    const int row  = blockIdx.x;           // b*NQ + q
    const int b    = row / NQ;
    const int h    = threadIdx.x >> 5;     // warp = head
    const int lane = threadIdx.x & 31;

    float logit = -1e30f;
    if (lane < 16) logit = attn[(size_t)row * (HEADS * 16) + h * 16 + lane];
    float mx = logit;
    #pragma unroll
    for (int o = 8; o >= 1; o >>= 1)
        mx = fmaxf(mx, __shfl_xor_sync(0xffffffffu, mx, o, 16));
    float e = (lane < 16) ? __expf(logit - mx) : 0.f;
    float s = e;
    #pragma unroll
    for (int o = 8; o >= 1; o >>= 1)
        s += __shfl_xor_sync(0xffffffffu, s, o, 16);

    if (lane < 16) {
        const float w = e / s;
        const int   j = lane;
        const int   l = j >> 2;

        const int HW[4]  = {92, 46, 23, 12};
        const int LST[4] = {0, 8464, 10580, 11109};
        const int   Ww = HW[l], Hh = HW[l], st = LST[l];
        const float fW = (float)Ww, fH = (float)Hh;

        const float2 rp = *reinterpret_cast<const float2*>(
            refp + (size_t)row * (LEVELS * 2) + 2 * l);
        const float2 of = *reinterpret_cast<const float2*>(
            off + (size_t)row * ED + h * 32 + 2 * j);

        const float x = (rp.x + of.x / fW) * fW - 0.5f;
        const float y = (rp.y + of.y / fH) * fH - 0.5f;

        const float x0f = floorf(x), y0f = floorf(y);
        const int   x0 = (int)x0f,   y0 = (int)y0f;
        const float wx1 = x - x0f,   wy1 = y - y0f;
        const float wx0 = 1.f - wx1, wy0 = 1.f - wy1;

        const bool xi0 = (x0 >= 0) && (x0 < Ww);
        const bool xi1 = (x0 + 1 >= 0) && (x0 + 1 < Ww);
        const bool yi0 = (y0 >= 0) && (y0 < Hh);
        const bool yi1 = (y0 + 1 >= 0) && (y0 + 1 < Hh);

        const int xc0 = min(max(x0, 0), Ww - 1);
        const int xc1 = min(max(x0 + 1, 0), Ww - 1);
        const int yc0 = min(max(y0, 0), Hh - 1);
        const int yc1 = min(max(y0 + 1, 0), Hh - 1);

        const int base = (b * NQ + st) * ED + h * 32;
        const int r0   = yc0 * Ww * ED;
        const int r1   = yc1 * Ww * ED;

        const int i00 = base + r0 + xc0 * ED;
        const int i01 = base + r0 + xc1 * ED;
        const int i10 = base + r1 + xc0 * ED;
        const int i11 = base + r1 + xc1 * ED;

        const float w00 = (xi0 && yi0) ? w * wx0 * wy0 : 0.f;
        const float w01 = (xi1 && yi0) ? w * wx1 * wy0 : 0.f;
        const float w10 = (xi0 && yi1) ? w * wx0 * wy1 : 0.f;
        const float w11 = (xi1 && yi1) ? w * wx1 * wy1 : 0.f;

        sOff[h][j][0] = make_int2(i00, i10);
        sOff[h][j][1] = make_int2(i01, i11);
        sWp[h][j][0]  = make_float2(w00, w10);
        sWp[h][j][1]  = make_float2(w01, w11);
    }
    __syncwarp();

    const int p    = lane >> 4;
    const int sub2 = (lane & 15) * 2;
    const float* vb = v + sub2;

    float ax = 0.f, ay = 0.f;
    #pragma unroll
    for (int j = 0; j < 16; j++) {
        const int2   o  = sOff[h][j][p];
        const float2 ww = sWp[h][j][p];
        const float2 v0 = *(const float2*)(vb + o.x);
        const float2 v1 = *(const float2*)(vb + o.y);
        ax += ww.x * v0.x + ww.y * v1.x;
        ay += ww.x * v0.y + ww.y * v1.y;
    }
    ax += __shfl_xor_sync(0xffffffffu, ax, 16);
    ay += __shfl_xor_sync(0xffffffffu, ay, 16);

    if (lane < 16) {
        float2 o;
        o.x = cvt_tf32f(ax);                 // pre-round for out-proj GEMM
        o.y = cvt_tf32f(ay);
        *(float2*)(samp + (size_t)row * ED + h * 32 + sub2) = o;
    }
}

// ---------------------------------------------------------------------------
// Launch
// ---------------------------------------------------------------------------
extern "C" void kernel_launch(void* const* d_in, const int* in_sizes, int n_in,
                              void* d_out, int out_size)
{
    const float* query  = (const float*)d_in[0];
    const float* value  = (const float*)d_in[1];
    const float* refpts = (const float*)d_in[2];
    // d_in[3] = spatial_shapes (int32) — compile-time constants here
    const float* W_val  = (const float*)d_in[4];
    const float* b_val  = (const float*)d_in[5];
    const float* W_off  = (const float*)d_in[6];
    const float* b_off  = (const float*)d_in[7];
    const float* W_attn = (const float*)d_in[8];
    const float* b_attn = (const float*)d_in[9];
    const float* W_out  = (const float*)d_in[10];
    const float* b_out  = (const float*)d_in[11];
    float* out = (float*)d_out;

    float *pv, *poff, *pattn, *psamp, *pqr, *pvr;
    float *twv, *two, *twa, *twu;
    cudaGetSymbolAddress((void**)&pv,    g_v);
    cudaGetSymbolAddress((void**)&poff,  g_off);
    cudaGetSymbolAddress((void**)&pattn, g_attn);
    cudaGetSymbolAddress((void**)&psamp, g_samp);
    cudaGetSymbolAddress((void**)&pqr,   g_qr);
    cudaGetSymbolAddress((void**)&pvr,   g_vr);
    cudaGetSymbolAddress((void**)&twv,   g_wt_val);
    cudaGetSymbolAddress((void**)&two,   g_wt_off);
    cudaGetSymbolAddress((void**)&twa,   g_wt_attn);
    cudaGetSymbolAddress((void**)&twu,   g_wt_out);

    const int SMEM = 2 * (128 * 36 + 64 * 36) * 4;   // 55296 B
    cudaFuncSetAttribute(gemm_proj_fused,
                         cudaFuncAttributeMaxDynamicSharedMemorySize, SMEM);
    cudaFuncSetAttribute(gemm_out,
                         cudaFuncAttributeMaxDynamicSharedMemorySize, SMEM);

    // 1) prep: round inputs to tf32; transpose+round weights
    const int N4 = MROWS * ED / 4;
    round2_tf32<<<1184, 256>>>(query, pqr, value, pvr, N4);
    transpose4<<<dim3(8, 8, 4), dim3(32, 8)>>>(W_val, W_off, W_attn, W_out,
                                               twv, two, twa, twu);

    // 2) all three projections in one launch (10 col tiles x 176 M tiles)
    gemm_proj_fused<<<dim3(10, MTILES), 256, SMEM>>>(
        pqr, pvr,
        twv, b_val,  pv,
        two, b_off,  poff,
        twa, b_attn, pattn,
        MROWS);

    // 3) sampling
    msda_sample<<<MROWS, HEADS * 32>>>(pv, poff, pattn, refpts, psamp);

    // 4) output projection + residual (residual = original fp32 query)
    gemm_out<<<dim3(4, MTILES), 256, SMEM>>>(psamp, twu, b_out, query, out, MROWS);
}